// round 17
// baseline (speedup 1.0000x reference)
#include <cuda_runtime.h>
#include <math.h>
#include <stdint.h>

// MarginalGaussianization forward on GB300 — single persistent kernel.
// Inputs: x [B,64] f32, x_values [64,1000] f32 (sorted linspace/row),
// cdf_values [64,1000] f32 (strictly increasing). Output: z [B,64] then log_det [B].
//
//  - One kernel launch total (guaranteed ncu visibility): main phase +
//    device-wide counter barrier + fused log-det reduce epilogue.
//  - 8 dim-groups x 18 chunks = 144 blocks x 512 threads. All blocks
//    co-resident (128KB smem -> 1 block/SM, 144 <= 148 SMs), so the spin
//    barrier cannot deadlock. Monotonic phase counter is graph-replay safe.
//  - TPB=512 -> 128-reg budget: no local-memory spills in the hot loop
//    (at 1024 threads the 64-reg cap likely forced LDL/STL per element).
//  - Hot path: 1-FMA bin guess + exact +/-1 fixup (searchsorted semantics),
//    one LDS.128/dim, branch-lean Giles erfinv, term = __logf(slope)+C+0.5z^2.

#define DIMS    64
#define NBK     1000
#define GROUPS  8
#define DPG     8
#define TPB     512
#define NCHUNK  18
#define NBLOCKS (NCHUNK * GROUPS)
#define BMAX    262144

#define SMEM_TAB_BYTES (DPG * NBK * 16)   // 128000

__device__ float g_partial[GROUPS * (size_t)BMAX];
__device__ unsigned g_ctr = 0u;           // monotonic cross-launch barrier counter

// ---------------- shared table build ----------------
// payload ent[j] = (x_l, slope, c_l, x_r); dinfo = (inv_step, bias)
__device__ __forceinline__ void build_table(float4* tab, float2* dinfo_s,
                                            const float* __restrict__ xv,
                                            const float* __restrict__ cdf,
                                            int d0, int tid)
{
    for (int idx = tid; idx < DPG * (NBK - 1); idx += TPB) {
        int k = idx / (NBK - 1);
        int j = idx - k * (NBK - 1);
        const float* xvk = xv  + (size_t)(d0 + k) * NBK;
        const float* ck  = cdf + (size_t)(d0 + k) * NBK;
        float xl = xvk[j], xr = xvk[j + 1];
        float cl = ck[j],  cr = ck[j + 1];
        float denom = xr - xl + 1e-12f;
        float s = (cr - cl) / denom;                          // matches reference math
        tab[k * NBK + j] = make_float4(xl, s, cl, xr);
    }
    if (tid < DPG) {
        const float* xvk = xv + (size_t)(d0 + tid) * NBK;
        float x0 = xvk[0], x1 = xvk[NBK - 1];
        float inv = (float)(NBK - 1) / (x1 - x0);
        dinfo_s[tid] = make_float2(inv, -x0 * inv);           // j_guess = fma(x, inv, bias)
    }
}

// ---------------- per-element hot path (exact searchsorted semantics) ----------------
__device__ __forceinline__ float gauss_term(float xk, float2 dik, const float4* tk, float& zz)
{
    // analytic bin guess on the linspace grid (provably within +/-1 of truth)
    int j = __float2int_rd(fmaf(xk, dik.x, dik.y));
    j = max(0, min(j, NBK - 2));

    float4 e = tk[j];                                         // (x_l, slope, c_l, x_r)

    // exact +/-1 fixup; reload only if some active lane moved (rare)
    int j2 = j + (int)(xk > e.w) - (int)(xk <= e.x);
    j2 = max(0, min(j2, NBK - 2));
    unsigned m = __activemask();
    if (__any_sync(m, j2 != j)) {
        if (j2 != j) e = tk[j2];
    }

    // u = c_l + slope*(x - x_l); t-clamp subsumes the reference's u-clip
    float u = fmaf(e.y, xk - e.x, e.z);
    float tt = fmaf(2.0f, u, -1.0f);
    tt = fminf(fmaxf(tt, -0.99999f), 0.99999f);

    // erfinv (Giles): central poly always; tail only if some lane needs it
    float w  = -__logf(fmaf(tt, -tt, 1.0f));                  // w in (0, ~10.82]
    float wc = w - 2.5f;

    float p =               2.81022636e-08f;
    p = fmaf(p, wc,         3.43273939e-07f);
    p = fmaf(p, wc,        -3.5233877e-06f);
    p = fmaf(p, wc,        -4.39150654e-06f);
    p = fmaf(p, wc,         0.00021858087f);
    p = fmaf(p, wc,        -0.00125372503f);
    p = fmaf(p, wc,        -0.00417768164f);
    p = fmaf(p, wc,         0.246640727f);
    p = fmaf(p, wc,         1.50140941f);

    if (__any_sync(m, w >= 5.0f)) {
        float wt = sqrtf(w) - 3.0f;
        float pt =              -0.000200214257f;
        pt = fmaf(pt, wt,        0.000100950558f);
        pt = fmaf(pt, wt,        0.00134934322f);
        pt = fmaf(pt, wt,       -0.00367342844f);
        pt = fmaf(pt, wt,        0.00573950773f);
        pt = fmaf(pt, wt,       -0.0076224613f);
        pt = fmaf(pt, wt,        0.00943887047f);
        pt = fmaf(pt, wt,        1.00167406f);
        pt = fmaf(pt, wt,        2.83297682f);
        p = (w < 5.0f) ? p : pt;
    }

    zz = 1.4142135623730951f * p * tt;                        // |z| <= 4.42 < 10: no clip

    // term = log(p_hat) - log(phi + 1e-12)
    //      = log(max(slope,1e-12)) + log(sqrt(2pi)) + 0.5*z^2   (err < 5e-8)
    float L = __logf(fmaxf(e.y, 1e-12f)) + 0.91893853320467274f;
    return fmaf(0.5f * zz, zz, L);
}

// ---------------- single persistent kernel ----------------
__global__ __launch_bounds__(TPB)
void mg_main(const float* __restrict__ x,
             const float* __restrict__ xv,
             const float* __restrict__ cdf,
             float* __restrict__ zout,
             int B, int spb)
{
    extern __shared__ char smem_raw[];
    float4* tab = (float4*)smem_raw;                          // [DPG][NBK]
    __shared__ float2 dinfo_s[DPG];

    const int tid = threadIdx.x;
    const int g   = blockIdx.y;
    const int d0  = g * DPG;

    build_table(tab, dinfo_s, xv, cdf, d0, tid);
    __syncthreads();

    float2 di[DPG];
    #pragma unroll
    for (int k = 0; k < DPG; k++) di[k] = dinfo_s[k];

    const int b0   = blockIdx.x * spb;
    const int bend = min(B, b0 + spb);

    // ================= phase 1: transform + per-group partials =================
    for (int b = b0 + tid; b < bend; b += TPB) {
        const float4* xp = (const float4*)(x + (size_t)b * DIMS + d0);
        float4 xa = xp[0];
        float4 xb = xp[1];
        float acc;
        float4 z0, z1;

        acc  = gauss_term(xa.x, di[0], tab + 0 * NBK, z0.x);
        acc += gauss_term(xa.y, di[1], tab + 1 * NBK, z0.y);
        acc += gauss_term(xa.z, di[2], tab + 2 * NBK, z0.z);
        acc += gauss_term(xa.w, di[3], tab + 3 * NBK, z0.w);

        float4* zp = (float4*)(zout + (size_t)b * DIMS + d0);
        zp[0] = z0;                                           // early store frees regs

        acc += gauss_term(xb.x, di[4], tab + 4 * NBK, z1.x);
        acc += gauss_term(xb.y, di[5], tab + 5 * NBK, z1.y);
        acc += gauss_term(xb.z, di[6], tab + 6 * NBK, z1.z);
        acc += gauss_term(xb.w, di[7], tab + 7 * NBK, z1.w);

        zp[1] = z1;
        g_partial[(size_t)g * B + b] = acc;
    }

    // ================= device-wide barrier (all 144 blocks co-resident) ========
    __syncthreads();                                          // block's partials issued
    if (tid == 0) {
        __threadfence();                                      // partials visible
        unsigned arrival = atomicAdd(&g_ctr, 1u);
        unsigned target  = (arrival / NBLOCKS + 1u) * NBLOCKS;
        while (*((volatile unsigned*)&g_ctr) < target) { }
        __threadfence();
    }
    __syncthreads();

    // ================= phase 2: fused log-det reduce ===========================
    float* ld = zout + (size_t)B * DIMS;
    const int bid  = blockIdx.y * gridDim.x + blockIdx.x;     // 0..143
    const int nthr = NBLOCKS * TPB;
    for (int s = bid * TPB + tid; s < B; s += nthr) {
        float sum = 0.0f;
        #pragma unroll
        for (int k = 0; k < GROUPS; k++) sum += g_partial[(size_t)k * B + s];
        ld[s] = sum;                                          // fixed order: deterministic
    }
}

extern "C" void kernel_launch(void* const* d_in, const int* in_sizes, int n_in,
                              void* d_out, int out_size)
{
    const float* x   = (const float*)d_in[0];
    const float* xv  = (const float*)d_in[1];
    const float* cdf = (const float*)d_in[2];
    float* out = (float*)d_out;

    const int B = in_sizes[0] / DIMS;

    static bool attr_set = false;
    if (!attr_set) {
        cudaFuncSetAttribute(mg_main, cudaFuncAttributeMaxDynamicSharedMemorySize, SMEM_TAB_BYTES);
        attr_set = true;
    }

    dim3 grid(NCHUNK, GROUPS);
    int spb = (B + NCHUNK - 1) / NCHUNK;
    mg_main<<<grid, TPB, SMEM_TAB_BYTES>>>(x, xv, cdf, out, B, spb);
}